// round 2
// baseline (speedup 1.0000x reference)
#include <cuda_runtime.h>

// ---------------- scratch (static device memory; no allocs allowed) ----------
__device__ float g_bufA[8 * 64 * 256 * 256];   // 33.5M floats
__device__ float g_bufB[8 * 64 * 256 * 256];   // 33.5M floats
__device__ float g_wT[2304 * 256];             // transposed conv weights (K, Cout)
__device__ float g_scale[256];
__device__ float g_shift[256];

__device__ __forceinline__ float lrelu(float v) { return v >= 0.f ? v : 0.2f * v; }

// ---------------- conv0: 3->64, 3x3 s1 p1, + bias + lrelu (naive) -----------
__global__ void conv0_kernel(const float* __restrict__ x,
                             const float* __restrict__ w,
                             const float* __restrict__ bias,
                             float* __restrict__ out)
{
    int i = blockIdx.x * 256 + threadIdx.x;          // over 8*64*256*256
    int xx = i & 255;
    int y  = (i >> 8) & 255;
    int oc = (i >> 16) & 63;
    int b  = i >> 22;
    float acc = bias[oc];
    const float* wp = w + oc * 27;
#pragma unroll
    for (int c = 0; c < 3; c++) {
        const float* xp = x + ((b * 3 + c) * 256) * 256;
#pragma unroll
        for (int ky = 0; ky < 3; ky++) {
            int iy = y + ky - 1;
            if ((unsigned)iy >= 256u) continue;
#pragma unroll
            for (int kx = 0; kx < 3; kx++) {
                int ix = xx + kx - 1;
                if ((unsigned)ix >= 256u) continue;
                acc = fmaf(__ldg(xp + iy * 256 + ix), wp[c * 9 + ky * 3 + kx], acc);
            }
        }
    }
    out[i] = lrelu(acc);
}

// ---------------- weight transpose: (Cout, K) -> (K, Cout) ------------------
__global__ void transpose_w(const float* __restrict__ w, float* __restrict__ wT,
                            int Cout, int K)
{
    int i = blockIdx.x * 256 + threadIdx.x;
    if (i >= Cout * K) return;
    int k = i / Cout;
    int oc = i - k * Cout;
    wT[i] = w[oc * K + k];
}

// ---------------- generic direct conv as implicit GEMM ----------------------
// Output tile: 128 pixels x BN_ out-channels, K chunked by 8.
// 256 threads: tx = t&15 owns 8 pixels, ty = t>>4 owns TN_ channels.
template <int KH, int KW, int STRIDE, int BN_, int TN_>
__global__ __launch_bounds__(256) void conv_gemm(
    const float* __restrict__ in, const float* __restrict__ wT,
    float* __restrict__ out,
    int Cin, int Cout, int Hin, int Win, int Hout, int Wout)
{
    const int K   = Cin * KH * KW;
    const int HWo = Hout * Wout;
    const int tileP  = blockIdx.x * 128;
    const int ocBase = blockIdx.y * BN_;

    __shared__ float As[8][128];
    __shared__ float Bs[8][BN_];

    const int t  = threadIdx.x;
    const int tx = t & 15;
    const int ty = t >> 4;

    float acc[8][TN_];
#pragma unroll
    for (int i = 0; i < 8; i++)
#pragma unroll
        for (int j = 0; j < TN_; j++) acc[i][j] = 0.f;

    for (int k0 = 0; k0 < K; k0 += 8) {
        // ---- stage A (im2col on the fly): 1024 elems, 4 per thread ----
#pragma unroll
        for (int l = t; l < 1024; l += 256) {
            int kk = l >> 7, pl = l & 127;
            int k  = k0 + kk;
            int c  = k / (KH * KW);
            int r  = k - c * (KH * KW);
            int ky = r / KW;
            int kx = r - ky * KW;
            int p  = tileP + pl;
            int bb = p / HWo;
            int pp = p - bb * HWo;
            int oy = pp / Wout;
            int ox = pp - oy * Wout;
            int iy = oy * STRIDE + ky - 1;
            int ix = ox * STRIDE + kx - 1;
            float v = 0.f;
            if ((unsigned)iy < (unsigned)Hin && (unsigned)ix < (unsigned)Win)
                v = in[((bb * Cin + c) * Hin + iy) * Win + ix];
            As[kk][pl] = v;
        }
        // ---- stage B: BN_*8 elems ----
#pragma unroll
        for (int l = t; l < BN_ * 8; l += 256) {
            int kk = l / BN_, oc = l - kk * BN_;
            Bs[kk][oc] = wT[(k0 + kk) * Cout + ocBase + oc];
        }
        __syncthreads();
#pragma unroll
        for (int kk = 0; kk < 8; kk++) {
            float a[8], bb[TN_];
#pragma unroll
            for (int i = 0; i < 8; i++) a[i] = As[kk][tx * 8 + i];
#pragma unroll
            for (int j = 0; j < TN_; j++) bb[j] = Bs[kk][ty * TN_ + j];
#pragma unroll
            for (int i = 0; i < 8; i++)
#pragma unroll
                for (int j = 0; j < TN_; j++)
                    acc[i][j] = fmaf(a[i], bb[j], acc[i][j]);
        }
        __syncthreads();
    }

    // ---- store raw conv result ----
    int p0 = tileP + tx * 8;
    int bb = p0 / HWo;
    int pp = p0 - bb * HWo;
#pragma unroll
    for (int j = 0; j < TN_; j++) {
        int oc = ocBase + ty * TN_ + j;
        float* op = out + (size_t)(bb * Cout + oc) * HWo + pp;
#pragma unroll
        for (int i = 0; i < 8; i++) op[i] = acc[i][j];
    }
}

// ---------------- BN (training mode): stats -> scale/shift ------------------
__global__ void bn_stats(const float* __restrict__ x,
                         const float* __restrict__ g, const float* __restrict__ bt,
                         int C, int HW, float* __restrict__ scale,
                         float* __restrict__ shift)
{
    int c = blockIdx.x;
    int t = threadIdx.x;
    float s = 0.f, sq = 0.f;
    for (int b = 0; b < 8; b++) {
        const float* p = x + (size_t)(b * C + c) * HW;
        for (int i = t; i < HW; i += 256) {
            float v = p[i];
            s += v;
            sq += v * v;
        }
    }
    __shared__ float ss[256], sqq[256];
    ss[t] = s; sqq[t] = sq;
    __syncthreads();
    for (int o = 128; o > 0; o >>= 1) {
        if (t < o) { ss[t] += ss[t + o]; sqq[t] += sqq[t + o]; }
        __syncthreads();
    }
    if (t == 0) {
        float n = 8.f * (float)HW;
        float m = ss[0] / n;
        float var = sqq[0] / n - m * m;
        float is = rsqrtf(var + 1e-5f);
        float sc = g[c] * is;
        scale[c] = sc;
        shift[c] = bt[c] - m * sc;
    }
}

__global__ void bn_apply(float* __restrict__ x, const float* __restrict__ scale,
                         const float* __restrict__ shift, int C, int HW, int total)
{
    int i = blockIdx.x * 256 + threadIdx.x;
    if (i >= total) return;
    int c = (i / HW) % C;
    float v = fmaf(x[i], scale[c], shift[c]);
    x[i] = v >= 0.f ? v : 0.2f * v;
}

// ---------------- head: router + top-1 expert MLP ---------------------------
// One block (256 threads) per token. fm: (8, 256, 64, 64).
__global__ __launch_bounds__(256) void head_kernel(
    const float* __restrict__ fm,
    const float* __restrict__ wg,      // (256, 12)
    const float* __restrict__ body_w,  // (256, 3072)
    const float* __restrict__ body_b,  // (3072)
    const float* __restrict__ ortho,   // (3072)
    const float* __restrict__ w1,      // (256, 32)
    const float* __restrict__ b1,      // (32)
    const float* __restrict__ w2,      // (32, 1)
    const float* __restrict__ b2,      // (1)
    float* __restrict__ out)           // (8*4096)
{
    int token = blockIdx.x;            // 0..32767
    int b  = token >> 12;
    int pp = token & 4095;
    int t  = threadIdx.x;

    __shared__ float tok[256];
    __shared__ float feat[256];
    __shared__ float lpart[12][8];
    __shared__ int eidx;

    tok[t] = fm[((size_t)(b * 256 + t) << 12) + pp];
    __syncthreads();

    // router logits (argmax of logits == argmax of softmax)
    int lane = t & 31, wrp = t >> 5;
    float tv = tok[t];
#pragma unroll
    for (int e = 0; e < 12; e++) {
        float p = tv * wg[t * 12 + e];
#pragma unroll
        for (int o = 16; o > 0; o >>= 1) p += __shfl_xor_sync(0xffffffffu, p, o);
        if (lane == 0) lpart[e][wrp] = p;
    }
    __syncthreads();
    if (t == 0) {
        int best = 0; float bv = -1e30f;
#pragma unroll
        for (int e = 0; e < 12; e++) {
            float s = 0.f;
#pragma unroll
            for (int w_ = 0; w_ < 8; w_++) s += lpart[e][w_];
            if (s > bv) { bv = s; best = e; }
        }
        eidx = best;
    }
    __syncthreads();
    int e = eidx;

    // selected-expert body column: feat[t] = lrelu(lrelu(tok . body_w[:,e*256+t] + b) * ortho)
    {
        int col = e * 256 + t;
        const float* wcol = body_w + col;
        float acc = body_b[col];
#pragma unroll 8
        for (int d = 0; d < 256; d++) acc = fmaf(tok[d], wcol[(size_t)d * 3072], acc);
        acc = lrelu(acc);
        acc = lrelu(acc * ortho[col]);
        feat[t] = acc;
    }
    __syncthreads();

    // shared classifier: 256 -> 32 (lrelu) -> 1
    if (t < 32) {
        float h = b1[t];
#pragma unroll 8
        for (int k = 0; k < 256; k++) h = fmaf(feat[k], w1[k * 32 + t], h);
        h = lrelu(h);
        float o = h * w2[t];
#pragma unroll
        for (int off = 16; off > 0; off >>= 1) o += __shfl_xor_sync(0xffffffffu, o, off);
        if (t == 0) out[token] = o + b2[0];
    }
}

// ---------------- launch ----------------------------------------------------
extern "C" void kernel_launch(void* const* d_in, const int* in_sizes, int n_in,
                              void* d_out, int out_size)
{
    const float* x        = (const float*)d_in[0];
    const float* conv0_w  = (const float*)d_in[1];
    const float* conv0_b  = (const float*)d_in[2];
    const float* conv1_w  = (const float*)d_in[3];
    const float* bn1_g    = (const float*)d_in[4];
    const float* bn1_b    = (const float*)d_in[5];
    const float* conv2_w  = (const float*)d_in[6];
    const float* bn2_g    = (const float*)d_in[7];
    const float* bn2_b    = (const float*)d_in[8];
    const float* conv3_w  = (const float*)d_in[9];
    const float* bn3_g    = (const float*)d_in[10];
    const float* bn3_b    = (const float*)d_in[11];
    const float* conv4_w  = (const float*)d_in[12];
    const float* bn4_g    = (const float*)d_in[13];
    const float* bn4_b    = (const float*)d_in[14];
    const float* conv5_w  = (const float*)d_in[15];
    const float* bn5_g    = (const float*)d_in[16];
    const float* bn5_b    = (const float*)d_in[17];
    const float* conv6_w  = (const float*)d_in[18];
    const float* bn6_g    = (const float*)d_in[19];
    const float* bn6_b    = (const float*)d_in[20];
    const float* w_gating = (const float*)d_in[21];
    const float* body_w   = (const float*)d_in[22];
    const float* body_b   = (const float*)d_in[23];
    const float* ortho_w  = (const float*)d_in[24];
    const float* cls_w1   = (const float*)d_in[25];
    const float* cls_b1   = (const float*)d_in[26];
    const float* cls_w2   = (const float*)d_in[27];
    const float* cls_b2   = (const float*)d_in[28];
    float* out = (float*)d_out;

    float *A, *Bb, *wT, *sc, *sh;
    cudaGetSymbolAddress((void**)&A,  g_bufA);
    cudaGetSymbolAddress((void**)&Bb, g_bufB);
    cudaGetSymbolAddress((void**)&wT, g_wT);
    cudaGetSymbolAddress((void**)&sc, g_scale);
    cudaGetSymbolAddress((void**)&sh, g_shift);

    // conv0: x -> A  (8,64,256,256), bias+lrelu fused
    conv0_kernel<<<(8 * 64 * 256 * 256) / 256, 256>>>(x, conv0_w, conv0_b, A);

    // conv1: 64->64, 4x4 s2 p1. A -> B (8,64,128,128)
    transpose_w<<<(64 * 1024 + 255) / 256, 256>>>(conv1_w, wT, 64, 1024);
    conv_gemm<4, 4, 2, 64, 4><<<dim3(131072 / 128, 1), 256>>>(
        A, wT, Bb, 64, 64, 256, 256, 128, 128);
    bn_stats<<<64, 256>>>(Bb, bn1_g, bn1_b, 64, 16384, sc, sh);
    bn_apply<<<(8 * 64 * 16384) / 256, 256>>>(Bb, sc, sh, 64, 16384, 8 * 64 * 16384);

    // conv2: 64->128, 3x3 s1 p1. B -> A (8,128,128,128)
    transpose_w<<<(128 * 576 + 255) / 256, 256>>>(conv2_w, wT, 128, 576);
    conv_gemm<3, 3, 1, 128, 8><<<dim3(131072 / 128, 1), 256>>>(
        Bb, wT, A, 64, 128, 128, 128, 128, 128);
    bn_stats<<<128, 256>>>(A, bn2_g, bn2_b, 128, 16384, sc, sh);
    bn_apply<<<(8 * 128 * 16384) / 256, 256>>>(A, sc, sh, 128, 16384, 8 * 128 * 16384);

    // conv3: 128->128, 4x4 s2 p1. A -> B (8,128,64,64)
    transpose_w<<<(128 * 2048 + 255) / 256, 256>>>(conv3_w, wT, 128, 2048);
    conv_gemm<4, 4, 2, 128, 8><<<dim3(32768 / 128, 1), 256>>>(
        A, wT, Bb, 128, 128, 128, 128, 64, 64);
    bn_stats<<<128, 256>>>(Bb, bn3_g, bn3_b, 128, 4096, sc, sh);
    bn_apply<<<(8 * 128 * 4096) / 256, 256>>>(Bb, sc, sh, 128, 4096, 8 * 128 * 4096);

    // conv4: 128->256, 3x3 s1 p1. B -> A (8,256,64,64)
    transpose_w<<<(256 * 1152 + 255) / 256, 256>>>(conv4_w, wT, 256, 1152);
    conv_gemm<3, 3, 1, 128, 8><<<dim3(32768 / 128, 2), 256>>>(
        Bb, wT, A, 128, 256, 64, 64, 64, 64);
    bn_stats<<<256, 256>>>(A, bn4_g, bn4_b, 256, 4096, sc, sh);
    bn_apply<<<(8 * 256 * 4096) / 256, 256>>>(A, sc, sh, 256, 4096, 8 * 256 * 4096);

    // conv5: 256->256, 3x3 s1 p1. A -> B
    transpose_w<<<(256 * 2304 + 255) / 256, 256>>>(conv5_w, wT, 256, 2304);
    conv_gemm<3, 3, 1, 128, 8><<<dim3(32768 / 128, 2), 256>>>(
        A, wT, Bb, 256, 256, 64, 64, 64, 64);
    bn_stats<<<256, 256>>>(Bb, bn5_g, bn5_b, 256, 4096, sc, sh);
    bn_apply<<<(8 * 256 * 4096) / 256, 256>>>(Bb, sc, sh, 256, 4096, 8 * 256 * 4096);

    // conv6: 256->256, 3x3 s1 p1. B -> A
    transpose_w<<<(256 * 2304 + 255) / 256, 256>>>(conv6_w, wT, 256, 2304);
    conv_gemm<3, 3, 1, 128, 8><<<dim3(32768 / 128, 2), 256>>>(
        Bb, wT, A, 256, 256, 64, 64, 64, 64);
    bn_stats<<<256, 256>>>(A, bn6_g, bn6_b, 256, 4096, sc, sh);
    bn_apply<<<(8 * 256 * 4096) / 256, 256>>>(A, sc, sh, 256, 4096, 8 * 256 * 4096);

    // head: router + top-1 expert (only the selected 256-column slice computed)
    head_kernel<<<32768, 256>>>(A, w_gating, body_w, body_b, ortho_w,
                                cls_w1, cls_b1, cls_w2, cls_b2, out);
}

// round 4
// speedup vs baseline: 1.5214x; 1.5214x over previous
#include <cuda_runtime.h>
#include <cuda_bf16.h>
#include <cstdint>

// ------------------ static scratch ------------------------------------------
__device__ __align__(256) float         g_raw[33554432];
__device__ __align__(256) __nv_bfloat16 g_A0[33554432], g_A1[33554432], g_A2[33554432];
__device__ __align__(256) __nv_bfloat16 g_B0[8388608],  g_B1[8388608],  g_B2[8388608];
__device__ __align__(256) __nv_bfloat16 g_w0[589824],   g_w1[589824],   g_w2[589824];
__device__ __align__(256) float         g_tok[8388608];
__device__ float g_part[2][256][8];
__device__ float g_scale[256], g_shift[256];

__device__ __forceinline__ float lrelu(float v) { return v >= 0.f ? v : 0.2f * v; }

// ------------------ asm helpers (all plain-sm_103-legal) --------------------
__device__ __forceinline__ uint32_t smem_u32(const void* p) {
    uint32_t a;
    asm("{ .reg .u64 t; cvta.to.shared.u64 t, %1; cvt.u32.u64 %0, t; }" : "=r"(a) : "l"(p));
    return a;
}
__device__ __forceinline__ void cp16(uint32_t dst, const void* src, int srcsize) {
    asm volatile("cp.async.cg.shared.global [%0], [%1], 16, %2;"
                 :: "r"(dst), "l"(src), "r"(srcsize) : "memory");
}
#define CP_COMMIT() asm volatile("cp.async.commit_group;" ::: "memory")
#define CP_WAIT1()  asm volatile("cp.async.wait_group 1;" ::: "memory")
#define CP_WAIT0()  asm volatile("cp.async.wait_group 0;" ::: "memory")

__device__ __forceinline__ void ldsm_x4(uint32_t* r, uint32_t a) {
    asm volatile("ldmatrix.sync.aligned.m8n8.x4.shared.b16 {%0,%1,%2,%3}, [%4];"
                 : "=r"(r[0]), "=r"(r[1]), "=r"(r[2]), "=r"(r[3]) : "r"(a));
}
__device__ __forceinline__ void ldsm_x2(uint32_t* r, uint32_t a) {
    asm volatile("ldmatrix.sync.aligned.m8n8.x2.shared.b16 {%0,%1}, [%2];"
                 : "=r"(r[0]), "=r"(r[1]) : "r"(a));
}
__device__ __forceinline__ void mma_bf16(float* c, const uint32_t* a, const uint32_t* b) {
    asm volatile("mma.sync.aligned.m16n8k16.row.col.f32.bf16.bf16.f32 "
                 "{%0,%1,%2,%3}, {%4,%5,%6,%7}, {%8,%9}, {%0,%1,%2,%3};"
                 : "+f"(c[0]), "+f"(c[1]), "+f"(c[2]), "+f"(c[3])
                 : "r"(a[0]), "r"(a[1]), "r"(a[2]), "r"(a[3]), "r"(b[0]), "r"(b[1]));
}
// swizzled byte offset within a 128B-row plane (row-major, 8 x 16B chunks/row)
__device__ __forceinline__ uint32_t swz(int row, int ck) {
    return (uint32_t)(row * 128 + ((ck ^ (row & 7)) * 16));
}

// ------------------ conv0: 3->64 3x3 s1 p1 + bias (raw, NO lrelu) -----------
__global__ void conv0_kernel(const float* __restrict__ x, const float* __restrict__ w,
                             const float* __restrict__ bias, float* __restrict__ out)
{
    int i = blockIdx.x * 256 + threadIdx.x;
    int xx = i & 255, y = (i >> 8) & 255, oc = (i >> 16) & 63, b = i >> 22;
    float acc = bias[oc];
    const float* wp = w + oc * 27;
#pragma unroll
    for (int c = 0; c < 3; c++) {
        const float* xp = x + ((b * 3 + c) * 256) * 256;
#pragma unroll
        for (int ky = 0; ky < 3; ky++) {
            int iy = y + ky - 1;
            if ((unsigned)iy >= 256u) continue;
#pragma unroll
            for (int kx = 0; kx < 3; kx++) {
                int ix = xx + kx - 1;
                if ((unsigned)ix >= 256u) continue;
                acc = fmaf(__ldg(xp + iy * 256 + ix), wp[c * 9 + ky * 3 + kx], acc);
            }
        }
    }
    out[i] = acc;
}

// ------------------ BN stats (deterministic) --------------------------------
__global__ void bnstat_kernel(const float* __restrict__ raw, int C, int HW)
{
    int c = blockIdx.x, b = blockIdx.y, t = threadIdx.x;
    const float* p = raw + (size_t)(b * C + c) * HW;
    float s = 0.f, q = 0.f;
    for (int i = t; i < HW; i += 256) { float v = p[i]; s += v; q += v * v; }
    __shared__ float ss[256], qq[256];
    ss[t] = s; qq[t] = q; __syncthreads();
    for (int o = 128; o > 0; o >>= 1) {
        if (t < o) { ss[t] += ss[t + o]; qq[t] += qq[t + o]; }
        __syncthreads();
    }
    if (t == 0) { g_part[0][c][b] = ss[0]; g_part[1][c][b] = qq[0]; }
}
__global__ void bnfin_kernel(const float* __restrict__ g, const float* __restrict__ bt, int C, int HW)
{
    int c = threadIdx.x;
    if (c >= C) return;
    float s = 0.f, q = 0.f;
#pragma unroll
    for (int b = 0; b < 8; b++) { s += g_part[0][c][b]; q += g_part[1][c][b]; }
    float n = 8.f * (float)HW;
    float m = s / n;
    float is = rsqrtf(q / n - m * m + 1e-5f);
    float sc = g[c] * is;
    g_scale[c] = sc; g_shift[c] = bt[c] - m * sc;
}

// ---- prep: [bn]+lrelu + NCHW->NHWC + 3-way bf16 split ----------------------
__global__ void prep_kernel(const float* __restrict__ raw, int useBn,
                            __nv_bfloat16* __restrict__ o0, __nv_bfloat16* __restrict__ o1,
                            __nv_bfloat16* __restrict__ o2, int C, int cShift, int H, int W)
{
    extern __shared__ float sp[];  // [32][C+1]
    int by = blockIdx.x, b = by / H, y = by - b * H;
    int x0 = blockIdx.y * 32, t = threadIdx.x, st = C + 1;
    for (int i = t; i < C * 32; i += 256) {
        int c = i >> 5, x = i & 31;
        float v = raw[((size_t)(b * C + c) * H + y) * W + x0 + x];
        if (useBn) v = fmaf(v, g_scale[c], g_shift[c]);
        sp[x * st + c] = lrelu(v);
    }
    __syncthreads();
    for (int i = t; i < C * 32; i += 256) {
        int x = i >> cShift, c = i & (C - 1);
        float v = sp[x * st + c];
        __nv_bfloat16 h0 = __float2bfloat16(v);
        float r1 = v - __bfloat162float(h0);
        __nv_bfloat16 h1 = __float2bfloat16(r1);
        float r2 = r1 - __bfloat162float(h1);
        size_t dst = ((size_t)(b * H + y) * W + x0 + x) * C + c;
        o0[dst] = h0; o1[dst] = h1; o2[dst] = __float2bfloat16(r2);
    }
}
// ---- prep_tok: bn+lrelu + NCHW->NHWC fp32 ----------------------------------
__global__ void prep_tok_kernel(const float* __restrict__ raw, float* __restrict__ tok,
                                int C, int cShift, int H, int W)
{
    extern __shared__ float sp[];
    int by = blockIdx.x, b = by / H, y = by - b * H;
    int x0 = blockIdx.y * 32, t = threadIdx.x, st = C + 1;
    for (int i = t; i < C * 32; i += 256) {
        int c = i >> 5, x = i & 31;
        float v = raw[((size_t)(b * C + c) * H + y) * W + x0 + x];
        sp[x * st + c] = lrelu(fmaf(v, g_scale[c], g_shift[c]));
    }
    __syncthreads();
    for (int i = t; i < C * 32; i += 256) {
        int x = i >> cShift, c = i & (C - 1);
        tok[((size_t)(b * H + y) * W + x0 + x) * C + c] = sp[x * st + c];
    }
}

// ---- weight split: OIHW fp32 -> (Cout, K) bf16 x3, k=(ky*KW+kx)*Cin+c ------
__global__ void wsplit_kernel(const float* __restrict__ w, int Cout, int Cin,
                              int KH, int KW, int total)
{
    int idx = blockIdx.x * 256 + threadIdx.x;
    if (idx >= total) return;
    int K = KH * KW * Cin;
    int oc = idx / K, k = idx - oc * K;
    int tap = k / Cin, c = k - tap * Cin;
    int ky = tap / KW, kx = tap - ky * KW;
    float v = w[((oc * Cin + c) * KH + ky) * KW + kx];
    __nv_bfloat16 h0 = __float2bfloat16(v);
    float r1 = v - __bfloat162float(h0);
    __nv_bfloat16 h1 = __float2bfloat16(r1);
    g_w0[idx] = h0; g_w1[idx] = h1; g_w2[idx] = __float2bfloat16(r1 - __bfloat162float(h1));
}

// ------------------ mma.sync implicit-GEMM conv -----------------------------
// CTA: 128 pixels x NBLK Cout. 8 warps (2x4). K chunks of 64, 2-stage cp.async.
// 6 split-products (a0b0,a0b1,a0b2,a1b0,a1b1,a2b0) -> fp32 accum (~exact).
template <int NBLK>
__global__ __launch_bounds__(256, 1) void conv_mma(
    const __nv_bfloat16* __restrict__ a0, const __nv_bfloat16* __restrict__ a1,
    const __nv_bfloat16* __restrict__ a2,
    const __nv_bfloat16* __restrict__ w0, const __nv_bfloat16* __restrict__ w1,
    const __nv_bfloat16* __restrict__ w2,
    float* __restrict__ raw,
    int cinShift, int KW, int stride, int Hin, int Win,
    int hwShift, int wShift, int Cout, int K, int nChunk)
{
    extern __shared__ char smem[];
    constexpr int APLANE = 16384;          // 128 rows * 128B
    constexpr int BPLANE = NBLK * 128;
    constexpr int SSTR = 3 * APLANE + 3 * BPLANE;
    constexpr int WN = NBLK / 4, WNF = WN / 8;

    const uint32_t sb = smem_u32(smem);
    const int t = threadIdx.x, lane = t & 31, wrp = t >> 5;
    const int warpM = wrp >> 2, warpN = wrp & 3;
    const int tileP = blockIdx.x * 128, ocBase = blockIdx.y * NBLK;
    const int bImg = tileP >> hwShift;
    const int pbase = tileP - (bImg << hwShift);

    float acc[4][WNF][4];
#pragma unroll
    for (int i = 0; i < 4; i++)
#pragma unroll
        for (int j = 0; j < WNF; j++)
#pragma unroll
            for (int k = 0; k < 4; k++) acc[i][j][k] = 0.f;

    auto load_chunk = [&](int ch, int stage) {
        int k0 = ch * 64;
        int tap = k0 >> cinShift, c0 = k0 - (tap << cinShift);
        int ky = tap / KW, kx = tap - ky * KW;
        uint32_t sbase = sb + stage * SSTR;
        // A: 3 planes * 128 rows * 8 chunks of 16B
        for (int id = t; id < 3072; id += 256) {
            int pl = id >> 10, rem = id & 1023;
            int row = rem >> 3, ck = rem & 7;
            int p = tileP + row;
            int b = p >> hwShift, pp = p - (b << hwShift);
            int oy = pp >> wShift, ox = pp - (oy << wShift);
            int iy = oy * stride - 1 + ky, ix = ox * stride - 1 + kx;
            bool ok = ((unsigned)iy < (unsigned)Hin) && ((unsigned)ix < (unsigned)Win);
            const __nv_bfloat16* pln = pl == 0 ? a0 : (pl == 1 ? a1 : a2);
            size_t off = ((((size_t)b * Hin + iy) * Win + ix) << cinShift) + c0 + ck * 8;
            const void* src = ok ? (const void*)(pln + off) : (const void*)pln;
            cp16(sbase + pl * APLANE + swz(row, ck), src, ok ? 16 : 0);
        }
        // B: 3 planes * NBLK rows * 8 chunks
        for (int id = t; id < 3 * NBLK * 8; id += 256) {
            int pl = id / (NBLK * 8), rem = id - pl * (NBLK * 8);
            int row = rem >> 3, ck = rem & 7;
            const __nv_bfloat16* pln = pl == 0 ? w0 : (pl == 1 ? w1 : w2);
            const void* src = pln + (size_t)(ocBase + row) * K + k0 + ck * 8;
            cp16(sbase + 3 * APLANE + pl * BPLANE + swz(row, ck), src, 16);
        }
    };

    load_chunk(0, 0);
    CP_COMMIT();

    int stage = 0;
#pragma unroll 1
    for (int ch = 0; ch < nChunk; ch++) {
        if (ch + 1 < nChunk) {
            load_chunk(ch + 1, stage ^ 1);
            CP_COMMIT();
            CP_WAIT1();
        } else {
            CP_WAIT0();
        }
        __syncthreads();

        uint32_t abase = sb + stage * SSTR;
        uint32_t bbase = abase + 3 * APLANE;
#pragma unroll
        for (int ks = 0; ks < 4; ks++) {
            uint32_t bfr[3][WNF][2];
#pragma unroll
            for (int p = 0; p < 3; p++)
#pragma unroll
                for (int nf = 0; nf < WNF; nf++) {
                    int r = warpN * WN + nf * 8 + (lane & 7);
                    int ck = ks * 2 + ((lane >> 3) & 1);
                    ldsm_x2(bfr[p][nf], bbase + p * BPLANE + swz(r, ck));
                }
#pragma unroll
            for (int p = 0; p < 3; p++) {
                uint32_t af[4][4];
#pragma unroll
                for (int mf = 0; mf < 4; mf++) {
                    int r = warpM * 64 + mf * 16 + (lane & 15);
                    int ck = ks * 2 + (lane >> 4);
                    ldsm_x4(af[mf], abase + p * APLANE + swz(r, ck));
                }
                int bc = 3 - p;   // a0:{b0,b1,b2} a1:{b0,b1} a2:{b0}
#pragma unroll
                for (int q = 0; q < 3; q++) {
                    if (q >= bc) break;
#pragma unroll
                    for (int mf = 0; mf < 4; mf++)
#pragma unroll
                        for (int nf = 0; nf < WNF; nf++)
                            mma_bf16(acc[mf][nf], af[mf], bfr[q][nf]);
                }
            }
        }
        __syncthreads();
        stage ^= 1;
    }

    // epilogue: frags -> raw NCHW fp32
    const size_t cs = (size_t)1 << hwShift;
#pragma unroll
    for (int mf = 0; mf < 4; mf++)
#pragma unroll
        for (int nf = 0; nf < WNF; nf++) {
            int m0 = warpM * 64 + mf * 16 + (lane >> 2);
            int n0 = warpN * WN + nf * 8 + (lane & 3) * 2;
            float* base = raw + (((size_t)bImg * Cout + ocBase + n0) << hwShift) + pbase;
            base[m0] = acc[mf][nf][0];
            base[cs + m0] = acc[mf][nf][1];
            base[m0 + 8] = acc[mf][nf][2];
            base[cs + m0 + 8] = acc[mf][nf][3];
        }
}

// ------------------ head: router + top-1 expert MLP -------------------------
__global__ __launch_bounds__(256) void head_kernel(
    const float* __restrict__ tokf, const float* __restrict__ wg,
    const float* __restrict__ body_w, const float* __restrict__ body_b,
    const float* __restrict__ ortho,
    const float* __restrict__ w1, const float* __restrict__ b1,
    const float* __restrict__ w2, const float* __restrict__ b2,
    float* __restrict__ out)
{
    int token = blockIdx.x, t = threadIdx.x;
    __shared__ float tok[256], feat[256], lpart[12][8];
    __shared__ int eidx;

    tok[t] = tokf[(size_t)token * 256 + t];
    __syncthreads();

    int lane = t & 31, wrp = t >> 5;
    float tv = tok[t];
#pragma unroll
    for (int e = 0; e < 12; e++) {
        float p = tv * wg[t * 12 + e];
#pragma unroll
        for (int o = 16; o > 0; o >>= 1) p += __shfl_xor_sync(0xffffffffu, p, o);
        if (lane == 0) lpart[e][wrp] = p;
    }
    __syncthreads();
    if (t == 0) {
        int best = 0; float bv = -1e30f;
#pragma unroll
        for (int e = 0; e < 12; e++) {
            float s = 0.f;
#pragma unroll
            for (int w_ = 0; w_ < 8; w_++) s += lpart[e][w_];
            if (s > bv) { bv = s; best = e; }
        }
        eidx = best;
    }
    __syncthreads();
    int e = eidx;
    {
        int col = e * 256 + t;
        const float* wcol = body_w + col;
        float acc = body_b[col];
#pragma unroll 8
        for (int d = 0; d < 256; d++) acc = fmaf(tok[d], wcol[(size_t)d * 3072], acc);
        acc = lrelu(acc);
        feat[t] = lrelu(acc * ortho[col]);
    }
    __syncthreads();
    if (t < 32) {
        float h = b1[t];
#pragma unroll 8
        for (int k = 0; k < 256; k++) h = fmaf(feat[k], w1[k * 32 + t], h);
        h = lrelu(h);
        float o = h * w2[t];
#pragma unroll
        for (int off = 16; off > 0; off >>= 1) o += __shfl_xor_sync(0xffffffffu, o, off);
        if (t == 0) out[token] = o + b2[0];
    }
}

// ------------------ launch --------------------------------------------------
extern "C" void kernel_launch(void* const* d_in, const int* in_sizes, int n_in,
                              void* d_out, int out_size)
{
    const float* x = (const float*)d_in[0];
    const float* c0w = (const float*)d_in[1];  const float* c0b = (const float*)d_in[2];
    const float* c1w = (const float*)d_in[3];  const float* g1 = (const float*)d_in[4];  const float* b1 = (const float*)d_in[5];
    const float* c2w = (const float*)d_in[6];  const float* g2 = (const float*)d_in[7];  const float* b2 = (const float*)d_in[8];
    const float* c3w = (const float*)d_in[9];  const float* g3 = (const float*)d_in[10]; const float* b3 = (const float*)d_in[11];
    const float* c4w = (const float*)d_in[12]; const float* g4 = (const float*)d_in[13]; const float* b4 = (const float*)d_in[14];
    const float* c5w = (const float*)d_in[15]; const float* g5 = (const float*)d_in[16]; const float* b5 = (const float*)d_in[17];
    const float* c6w = (const float*)d_in[18]; const float* g6 = (const float*)d_in[19]; const float* b6 = (const float*)d_in[20];
    const float* wg = (const float*)d_in[21];
    const float* bw = (const float*)d_in[22]; const float* bb = (const float*)d_in[23];
    const float* ow = (const float*)d_in[24];
    const float* cw1 = (const float*)d_in[25]; const float* cb1 = (const float*)d_in[26];
    const float* cw2 = (const float*)d_in[27]; const float* cb2 = (const float*)d_in[28];
    float* out = (float*)d_out;

    float *raw, *tok;
    __nv_bfloat16 *A0, *A1, *A2, *B0, *B1, *B2, *w0, *w1, *w2;
    cudaGetSymbolAddress((void**)&raw, g_raw);
    cudaGetSymbolAddress((void**)&tok, g_tok);
    cudaGetSymbolAddress((void**)&A0, g_A0); cudaGetSymbolAddress((void**)&A1, g_A1);
    cudaGetSymbolAddress((void**)&A2, g_A2);
    cudaGetSymbolAddress((void**)&B0, g_B0); cudaGetSymbolAddress((void**)&B1, g_B1);
    cudaGetSymbolAddress((void**)&B2, g_B2);
    cudaGetSymbolAddress((void**)&w0, g_w0); cudaGetSymbolAddress((void**)&w1, g_w1);
    cudaGetSymbolAddress((void**)&w2, g_w2);

    const int SM64 = 2 * (3 * 16384 + 3 * 64 * 128);    // 147456
    const int SM128 = 2 * (3 * 16384 + 3 * 128 * 128);  // 196608
    cudaFuncSetAttribute(conv_mma<64>, cudaFuncAttributeMaxDynamicSharedMemorySize, SM64);
    cudaFuncSetAttribute(conv_mma<128>, cudaFuncAttributeMaxDynamicSharedMemorySize, SM128);

    // conv0 -> raw; prep (lrelu+split) -> A planes (NHWC, C=64, 256x256)
    conv0_kernel<<<33554432 / 256, 256>>>(x, c0w, c0b, raw);
    prep_kernel<<<dim3(8 * 256, 8), 256, 32 * 65 * 4>>>(raw, 0, A0, A1, A2, 64, 6, 256, 256);

    // conv1: 64->64 4x4 s2 : A -> raw(64@128^2)
    wsplit_kernel<<<(64 * 1024 + 255) / 256, 256>>>(c1w, 64, 64, 4, 4, 65536);
    conv_mma<64><<<dim3(1024, 1), 256, SM64>>>(A0, A1, A2, w0, w1, w2, raw,
        6, 4, 2, 256, 256, 14, 7, 64, 1024, 16);
    bnstat_kernel<<<dim3(64, 8), 256>>>(raw, 64, 16384);
    bnfin_kernel<<<1, 64>>>(g1, b1, 64, 16384);
    prep_kernel<<<dim3(8 * 128, 4), 256, 32 * 65 * 4>>>(raw, 1, B0, B1, B2, 64, 6, 128, 128);

    // conv2: 64->128 3x3 s1 : B -> raw(128@128^2)
    wsplit_kernel<<<(128 * 576 + 255) / 256, 256>>>(c2w, 128, 64, 3, 3, 73728);
    conv_mma<128><<<dim3(1024, 1), 256, SM128>>>(B0, B1, B2, w0, w1, w2, raw,
        6, 3, 1, 128, 128, 14, 7, 128, 576, 9);
    bnstat_kernel<<<dim3(128, 8), 256>>>(raw, 128, 16384);
    bnfin_kernel<<<1, 128>>>(g2, b2, 128, 16384);
    prep_kernel<<<dim3(8 * 128, 4), 256, 32 * 129 * 4>>>(raw, 1, A0, A1, A2, 128, 7, 128, 128);

    // conv3: 128->128 4x4 s2 : A -> raw(128@64^2)
    wsplit_kernel<<<(128 * 2048 + 255) / 256, 256>>>(c3w, 128, 128, 4, 4, 262144);
    conv_mma<128><<<dim3(256, 1), 256, SM128>>>(A0, A1, A2, w0, w1, w2, raw,
        7, 4, 2, 128, 128, 12, 6, 128, 2048, 32);
    bnstat_kernel<<<dim3(128, 8), 256>>>(raw, 128, 4096);
    bnfin_kernel<<<1, 128>>>(g3, b3, 128, 4096);
    prep_kernel<<<dim3(8 * 64, 2), 256, 32 * 129 * 4>>>(raw, 1, B0, B1, B2, 128, 7, 64, 64);

    // conv4: 128->256 3x3 s1 : B -> raw(256@64^2)
    wsplit_kernel<<<(256 * 1152 + 255) / 256, 256>>>(c4w, 256, 128, 3, 3, 294912);
    conv_mma<128><<<dim3(256, 2), 256, SM128>>>(B0, B1, B2, w0, w1, w2, raw,
        7, 3, 1, 64, 64, 12, 6, 256, 1152, 18);
    bnstat_kernel<<<dim3(256, 8), 256>>>(raw, 256, 4096);
    bnfin_kernel<<<1, 256>>>(g4, b4, 256, 4096);
    prep_kernel<<<dim3(8 * 64, 2), 256, 32 * 257 * 4>>>(raw, 1, A0, A1, A2, 256, 8, 64, 64);

    // conv5: 256->256 3x3 s1 : A -> raw
    wsplit_kernel<<<(256 * 2304 + 255) / 256, 256>>>(c5w, 256, 256, 3, 3, 589824);
    conv_mma<128><<<dim3(256, 2), 256, SM128>>>(A0, A1, A2, w0, w1, w2, raw,
        8, 3, 1, 64, 64, 12, 6, 256, 2304, 36);
    bnstat_kernel<<<dim3(256, 8), 256>>>(raw, 256, 4096);
    bnfin_kernel<<<1, 256>>>(g5, b5, 256, 4096);
    prep_kernel<<<dim3(8 * 64, 2), 256, 32 * 257 * 4>>>(raw, 1, B0, B1, B2, 256, 8, 64, 64);

    // conv6: 256->256 3x3 s1 : B -> raw
    wsplit_kernel<<<(256 * 2304 + 255) / 256, 256>>>(c6w, 256, 256, 3, 3, 589824);
    conv_mma<128><<<dim3(256, 2), 256, SM128>>>(B0, B1, B2, w0, w1, w2, raw,
        8, 3, 1, 64, 64, 12, 6, 256, 2304, 36);
    bnstat_kernel<<<dim3(256, 8), 256>>>(raw, 256, 4096);
    bnfin_kernel<<<1, 256>>>(g6, b6, 256, 4096);
    prep_tok_kernel<<<dim3(8 * 64, 2), 256, 32 * 257 * 4>>>(raw, tok, 256, 8, 64, 64);

    // head
    head_kernel<<<32768, 256>>>(tok, wg, bw, bb, ow, cw1, cb1, cw2, cb2, out);
}

// round 5
// speedup vs baseline: 2.5959x; 1.7062x over previous
#include <cuda_runtime.h>
#include <cuda_fp16.h>
#include <cstdint>

// ------------------ static scratch ------------------------------------------
__device__ __align__(256) float  g_raw[33554432];          // raw conv out / feat scratch
__device__ __align__(256) __half g_A0[33554432], g_A1[33554432];
__device__ __align__(256) __half g_B0[8388608],  g_B1[8388608];
__device__ __align__(256) __half g_w0[589824],   g_w1[589824];
__device__ __align__(256) float  g_tok[8388608];
__device__ float g_part[2][256][8];
__device__ float g_scale[256], g_shift[256];
__device__ int g_eidx[32768], g_list[32768];
__device__ int g_cnt[12], g_off[12], g_fill[12];

__device__ __forceinline__ float lrelu(float v) { return v >= 0.f ? v : 0.2f * v; }

// ------------------ asm helpers ---------------------------------------------
__device__ __forceinline__ uint32_t smem_u32(const void* p) {
    uint32_t a;
    asm("{ .reg .u64 t; cvta.to.shared.u64 t, %1; cvt.u32.u64 %0, t; }" : "=r"(a) : "l"(p));
    return a;
}
__device__ __forceinline__ void cp16(uint32_t dst, const void* src, int srcsize) {
    asm volatile("cp.async.cg.shared.global [%0], [%1], 16, %2;"
                 :: "r"(dst), "l"(src), "r"(srcsize) : "memory");
}
#define CP_COMMIT() asm volatile("cp.async.commit_group;" ::: "memory")
#define CP_WAIT1()  asm volatile("cp.async.wait_group 1;" ::: "memory")
#define CP_WAIT0()  asm volatile("cp.async.wait_group 0;" ::: "memory")

__device__ __forceinline__ void ldsm_x4(uint32_t* r, uint32_t a) {
    asm volatile("ldmatrix.sync.aligned.m8n8.x4.shared.b16 {%0,%1,%2,%3}, [%4];"
                 : "=r"(r[0]), "=r"(r[1]), "=r"(r[2]), "=r"(r[3]) : "r"(a));
}
__device__ __forceinline__ void ldsm_x2(uint32_t* r, uint32_t a) {
    asm volatile("ldmatrix.sync.aligned.m8n8.x2.shared.b16 {%0,%1}, [%2];"
                 : "=r"(r[0]), "=r"(r[1]) : "r"(a));
}
__device__ __forceinline__ void mma_f16(float* c, const uint32_t* a, const uint32_t* b) {
    asm volatile("mma.sync.aligned.m16n8k16.row.col.f32.f16.f16.f32 "
                 "{%0,%1,%2,%3}, {%4,%5,%6,%7}, {%8,%9}, {%0,%1,%2,%3};"
                 : "+f"(c[0]), "+f"(c[1]), "+f"(c[2]), "+f"(c[3])
                 : "r"(a[0]), "r"(a[1]), "r"(a[2]), "r"(a[3]), "r"(b[0]), "r"(b[1]));
}
__device__ __forceinline__ uint32_t swz(int row, int ck) {
    return (uint32_t)(row * 128 + ((ck ^ (row & 7)) * 16));
}

// ------------------ conv0: 3->64 3x3 s1 p1 + bias (raw, NO lrelu) -----------
__global__ void conv0_kernel(const float* __restrict__ x, const float* __restrict__ w,
                             const float* __restrict__ bias, float* __restrict__ out)
{
    int i = blockIdx.x * 256 + threadIdx.x;
    int xx = i & 255, y = (i >> 8) & 255, oc = (i >> 16) & 63, b = i >> 22;
    float acc = bias[oc];
    const float* wp = w + oc * 27;
#pragma unroll
    for (int c = 0; c < 3; c++) {
        const float* xp = x + ((b * 3 + c) * 256) * 256;
#pragma unroll
        for (int ky = 0; ky < 3; ky++) {
            int iy = y + ky - 1;
            if ((unsigned)iy >= 256u) continue;
#pragma unroll
            for (int kx = 0; kx < 3; kx++) {
                int ix = xx + kx - 1;
                if ((unsigned)ix >= 256u) continue;
                acc = fmaf(__ldg(xp + iy * 256 + ix), wp[c * 9 + ky * 3 + kx], acc);
            }
        }
    }
    out[i] = acc;
}

// ------------------ BN stats (deterministic) --------------------------------
__global__ void bnstat_kernel(const float* __restrict__ raw, int C, int HW)
{
    int c = blockIdx.x, b = blockIdx.y, t = threadIdx.x;
    const float* p = raw + (size_t)(b * C + c) * HW;
    float s = 0.f, q = 0.f;
    for (int i = t; i < HW; i += 256) { float v = p[i]; s += v; q += v * v; }
    __shared__ float ss[256], qq[256];
    ss[t] = s; qq[t] = q; __syncthreads();
    for (int o = 128; o > 0; o >>= 1) {
        if (t < o) { ss[t] += ss[t + o]; qq[t] += qq[t + o]; }
        __syncthreads();
    }
    if (t == 0) { g_part[0][c][b] = ss[0]; g_part[1][c][b] = qq[0]; }
}
__global__ void bnfin_kernel(const float* __restrict__ g, const float* __restrict__ bt, int C, int HW)
{
    int c = threadIdx.x;
    if (c >= C) return;
    float s = 0.f, q = 0.f;
#pragma unroll
    for (int b = 0; b < 8; b++) { s += g_part[0][c][b]; q += g_part[1][c][b]; }
    float n = 8.f * (float)HW;
    float m = s / n;
    float is = rsqrtf(q / n - m * m + 1e-5f);
    float sc = g[c] * is;
    g_scale[c] = sc; g_shift[c] = bt[c] - m * sc;
}

// ---- prep: [bn]+lrelu + NCHW->NHWC + 2-way fp16 split ----------------------
__global__ void prep_kernel(const float* __restrict__ raw, int useBn,
                            __half* __restrict__ o0, __half* __restrict__ o1,
                            int C, int cShift, int H, int W)
{
    extern __shared__ float sp[];  // [32][C+1]
    int by = blockIdx.x, b = by / H, y = by - b * H;
    int x0 = blockIdx.y * 32, t = threadIdx.x, st = C + 1;
    for (int i = t; i < C * 32; i += 256) {
        int c = i >> 5, x = i & 31;
        float v = raw[((size_t)(b * C + c) * H + y) * W + x0 + x];
        if (useBn) v = fmaf(v, g_scale[c], g_shift[c]);
        sp[x * st + c] = lrelu(v);
    }
    __syncthreads();
    for (int i = t; i < C * 32; i += 256) {
        int x = i >> cShift, c = i & (C - 1);
        float v = sp[x * st + c];
        __half h0 = __float2half_rn(v);
        float r1 = v - __half2float(h0);
        size_t dst = ((size_t)(b * H + y) * W + x0 + x) * C + c;
        o0[dst] = h0; o1[dst] = __float2half_rn(r1);
    }
}
__global__ void prep_tok_kernel(const float* __restrict__ raw, float* __restrict__ tok,
                                int C, int cShift, int H, int W)
{
    extern __shared__ float sp[];
    int by = blockIdx.x, b = by / H, y = by - b * H;
    int x0 = blockIdx.y * 32, t = threadIdx.x, st = C + 1;
    for (int i = t; i < C * 32; i += 256) {
        int c = i >> 5, x = i & 31;
        float v = raw[((size_t)(b * C + c) * H + y) * W + x0 + x];
        sp[x * st + c] = lrelu(fmaf(v, g_scale[c], g_shift[c]));
    }
    __syncthreads();
    for (int i = t; i < C * 32; i += 256) {
        int x = i >> cShift, c = i & (C - 1);
        tok[((size_t)(b * H + y) * W + x0 + x) * C + c] = sp[x * st + c];
    }
}

// ---- weight split: OIHW fp32 -> (Cout, K) fp16 x2, k=(ky*KW+kx)*Cin+c ------
__global__ void wsplit_kernel(const float* __restrict__ w, int Cout, int Cin,
                              int KH, int KW, int total)
{
    int idx = blockIdx.x * 256 + threadIdx.x;
    if (idx >= total) return;
    int K = KH * KW * Cin;
    int oc = idx / K, k = idx - oc * K;
    int tap = k / Cin, c = k - tap * Cin;
    int ky = tap / KW, kx = tap - ky * KW;
    float v = w[((oc * Cin + c) * KH + ky) * KW + kx];
    __half h0 = __float2half_rn(v);
    float r1 = v - __half2float(h0);
    g_w0[idx] = h0; g_w1[idx] = __float2half_rn(r1);
}

// ------------------ mma.sync fp16 implicit-GEMM conv ------------------------
// CTA: 128 px x 64 Cout, 8 warps (2x4), K chunk 64, 2-stage cp.async, 2 CTA/SM.
// products a0b0, a0b1, a1b0 -> fp32 accum (error ~2^-23/layer).
template <int NBLK>
__global__ __launch_bounds__(256, 2) void conv_mma(
    const __half* __restrict__ a0, const __half* __restrict__ a1,
    const __half* __restrict__ w0, const __half* __restrict__ w1,
    float* __restrict__ raw,
    int cinShift, int KW, int stride, int Hin, int Win,
    int hwShift, int wShift, int Cout, int K, int nChunk)
{
    extern __shared__ char smem[];
    constexpr int APLANE = 16384;
    constexpr int BPLANE = NBLK * 128;
    constexpr int SSTR = 2 * APLANE + 2 * BPLANE;
    constexpr int WN = NBLK / 4, WNF = WN / 8;

    const uint32_t sb = smem_u32(smem);
    const int t = threadIdx.x, lane = t & 31, wrp = t >> 5;
    const int warpM = wrp >> 2, warpN = wrp & 3;
    const int tileP = blockIdx.x * 128, ocBase = blockIdx.y * NBLK;
    const int bImg = tileP >> hwShift;
    const int pbase = tileP - (bImg << hwShift);

    float acc[4][WNF][4];
#pragma unroll
    for (int i = 0; i < 4; i++)
#pragma unroll
        for (int j = 0; j < WNF; j++)
#pragma unroll
            for (int k = 0; k < 4; k++) acc[i][j][k] = 0.f;

    auto load_chunk = [&](int ch, int stage) {
        int k0 = ch * 64;
        int tap = k0 >> cinShift, c0 = k0 - (tap << cinShift);
        int ky = tap / KW, kx = tap - ky * KW;
        uint32_t sbase = sb + stage * SSTR;
        for (int id = t; id < 2048; id += 256) {
            int pl = id >> 10, rem = id & 1023;
            int row = rem >> 3, ck = rem & 7;
            int p = tileP + row;
            int b = p >> hwShift, pp = p - (b << hwShift);
            int oy = pp >> wShift, ox = pp - (oy << wShift);
            int iy = oy * stride - 1 + ky, ix = ox * stride - 1 + kx;
            bool ok = ((unsigned)iy < (unsigned)Hin) && ((unsigned)ix < (unsigned)Win);
            const __half* pln = pl == 0 ? a0 : a1;
            size_t off = ((((size_t)b * Hin + iy) * Win + ix) << cinShift) + c0 + ck * 8;
            const void* src = ok ? (const void*)(pln + off) : (const void*)pln;
            cp16(sbase + pl * APLANE + swz(row, ck), src, ok ? 16 : 0);
        }
        for (int id = t; id < 2 * NBLK * 8; id += 256) {
            int pl = id / (NBLK * 8), rem = id - pl * (NBLK * 8);
            int row = rem >> 3, ck = rem & 7;
            const __half* pln = pl == 0 ? w0 : w1;
            const void* src = pln + (size_t)(ocBase + row) * K + k0 + ck * 8;
            cp16(sbase + 2 * APLANE + pl * BPLANE + swz(row, ck), src, 16);
        }
    };

    load_chunk(0, 0);
    CP_COMMIT();

    int stage = 0;
#pragma unroll 1
    for (int ch = 0; ch < nChunk; ch++) {
        if (ch + 1 < nChunk) {
            load_chunk(ch + 1, stage ^ 1);
            CP_COMMIT();
            CP_WAIT1();
        } else {
            CP_WAIT0();
        }
        __syncthreads();

        uint32_t abase = sb + stage * SSTR;
        uint32_t bbase = abase + 2 * APLANE;
#pragma unroll
        for (int ks = 0; ks < 4; ks++) {
            uint32_t bfr[2][WNF][2];
#pragma unroll
            for (int p = 0; p < 2; p++)
#pragma unroll
                for (int nf = 0; nf < WNF; nf++) {
                    int r = warpN * WN + nf * 8 + (lane & 7);
                    int ck = ks * 2 + ((lane >> 3) & 1);
                    ldsm_x2(bfr[p][nf], bbase + p * BPLANE + swz(r, ck));
                }
#pragma unroll
            for (int p = 0; p < 2; p++) {
                uint32_t af[4][4];
#pragma unroll
                for (int mf = 0; mf < 4; mf++) {
                    int r = warpM * 64 + mf * 16 + (lane & 15);
                    int ck = ks * 2 + (lane >> 4);
                    ldsm_x4(af[mf], abase + p * APLANE + swz(r, ck));
                }
                int nq = 2 - p;   // a0:{b0,b1}  a1:{b0}
#pragma unroll
                for (int q = 0; q < 2; q++) {
                    if (q >= nq) break;
#pragma unroll
                    for (int mf = 0; mf < 4; mf++)
#pragma unroll
                        for (int nf = 0; nf < WNF; nf++)
                            mma_f16(acc[mf][nf], af[mf], bfr[q][nf]);
                }
            }
        }
        __syncthreads();
        stage ^= 1;
    }

    const size_t cs = (size_t)1 << hwShift;
#pragma unroll
    for (int mf = 0; mf < 4; mf++)
#pragma unroll
        for (int nf = 0; nf < WNF; nf++) {
            int m0 = warpM * 64 + mf * 16 + (lane >> 2);
            int n0 = warpN * WN + nf * 8 + (lane & 3) * 2;
            float* base = raw + (((size_t)bImg * Cout + ocBase + n0) << hwShift) + pbase;
            base[m0] = acc[mf][nf][0];
            base[cs + m0] = acc[mf][nf][1];
            base[m0 + 8] = acc[mf][nf][2];
            base[cs + m0 + 8] = acc[mf][nf][3];
        }
}

// ------------------ head: router -> group -> GEMM -> classifier -------------
__global__ void zero_cnt_kernel() { if (threadIdx.x < 12) g_cnt[threadIdx.x] = 0; }

__global__ __launch_bounds__(256) void router_kernel(
    const float* __restrict__ tok, const float* __restrict__ wg)
{
    int warp = (blockIdx.x * 256 + threadIdx.x) >> 5;
    int lane = threadIdx.x & 31;
    if (warp >= 32768) return;
    const float* tp = tok + (size_t)warp * 256;
    float l[12];
#pragma unroll
    for (int e = 0; e < 12; e++) l[e] = 0.f;
#pragma unroll
    for (int i = 0; i < 8; i++) {
        int d = lane + 32 * i;
        float tv = tp[d];
        const float* w = wg + d * 12;
#pragma unroll
        for (int e = 0; e < 12; e++) l[e] = fmaf(tv, __ldg(w + e), l[e]);
    }
#pragma unroll
    for (int e = 0; e < 12; e++)
#pragma unroll
        for (int o = 16; o > 0; o >>= 1) l[e] += __shfl_xor_sync(0xffffffffu, l[e], o);
    if (lane == 0) {
        int best = 0; float bv = l[0];
#pragma unroll
        for (int e = 1; e < 12; e++) if (l[e] > bv) { bv = l[e]; best = e; }
        g_eidx[warp] = best;
        atomicAdd(&g_cnt[best], 1);
    }
}
__global__ void offsets_kernel()
{
    if (threadIdx.x == 0) {
        int s = 0;
        for (int e = 0; e < 12; e++) { g_off[e] = s; g_fill[e] = s; s += g_cnt[e]; }
    }
}
__global__ void scatter_kernel()
{
    int tkn = blockIdx.x * 256 + threadIdx.x;
    if (tkn >= 32768) return;
    int slot = atomicAdd(&g_fill[g_eidx[tkn]], 1);
    g_list[slot] = tkn;
}

// body GEMM: per (expert, 128-token tile): feat = lrelu(lrelu(tok@W_e + b)*ortho)
__global__ __launch_bounds__(512) void body_kernel(
    const float* __restrict__ tok, const float* __restrict__ bw,
    const float* __restrict__ bb, const float* __restrict__ ow,
    float* __restrict__ feat)
{
    int e = blockIdx.y;
    int nt = g_cnt[e];
    int m0 = blockIdx.x * 128;
    if (m0 >= nt) return;
    __shared__ float As[8][132];
    __shared__ float Bs[8][256];
    __shared__ int stok[128];
    int t = threadIdx.x;
    if (t < 128) {
        int idx = m0 + t;
        stok[t] = g_list[g_off[e] + (idx < nt ? idx : 0)];
    }
    __syncthreads();
    int tx = t & 15, ty = t >> 4;
    float acc[8][8];
#pragma unroll
    for (int i = 0; i < 8; i++)
#pragma unroll
        for (int j = 0; j < 8; j++) acc[i][j] = 0.f;

    for (int k0 = 0; k0 < 256; k0 += 8) {
        for (int i = t; i < 1024; i += 512) {
            int kk = i & 7, m = i >> 3;
            As[kk][m] = tok[(size_t)stok[m] * 256 + k0 + kk];
        }
        for (int i = t; i < 2048; i += 512) {
            int kk = i >> 8, n = i & 255;
            Bs[kk][n] = bw[(size_t)(k0 + kk) * 3072 + e * 256 + n];
        }
        __syncthreads();
#pragma unroll
        for (int kk = 0; kk < 8; kk++) {
            float a[8], b[8];
#pragma unroll
            for (int i = 0; i < 8; i++) a[i] = As[kk][tx * 8 + i];
#pragma unroll
            for (int j = 0; j < 8; j++) b[j] = Bs[kk][ty * 8 + j];
#pragma unroll
            for (int i = 0; i < 8; i++)
#pragma unroll
                for (int j = 0; j < 8; j++) acc[i][j] = fmaf(a[i], b[j], acc[i][j]);
        }
        __syncthreads();
    }
#pragma unroll
    for (int i = 0; i < 8; i++) {
        if (m0 + tx * 8 + i >= nt) continue;
        int token = stok[tx * 8 + i];
#pragma unroll
        for (int j = 0; j < 8; j++) {
            int n = ty * 8 + j, col = e * 256 + n;
            float v = acc[i][j] + bb[col];
            v = lrelu(v);
            v = lrelu(v * ow[col]);
            feat[(size_t)token * 256 + n] = v;
        }
    }
}

// classifier: warp per token, 256 -> 32 (lrelu) -> 1
__global__ __launch_bounds__(256) void cls_kernel(
    const float* __restrict__ feat, const float* __restrict__ w1,
    const float* __restrict__ b1, const float* __restrict__ w2,
    const float* __restrict__ b2, float* __restrict__ out)
{
    int warp = (blockIdx.x * 256 + threadIdx.x) >> 5;
    int lane = threadIdx.x & 31;
    if (warp >= 32768) return;
    __shared__ float sf[8][256];
    int wl = threadIdx.x >> 5;
    const float* fp = feat + (size_t)warp * 256;
    for (int i = lane; i < 256; i += 32) sf[wl][i] = fp[i];
    __syncwarp();
    float h = b1[lane];
#pragma unroll 8
    for (int d = 0; d < 256; d++) h = fmaf(sf[wl][d], w1[d * 32 + lane], h);
    h = lrelu(h) * w2[lane];
#pragma unroll
    for (int o = 16; o > 0; o >>= 1) h += __shfl_xor_sync(0xffffffffu, h, o);
    if (lane == 0) out[warp] = h + b2[0];
}

// ------------------ launch --------------------------------------------------
extern "C" void kernel_launch(void* const* d_in, const int* in_sizes, int n_in,
                              void* d_out, int out_size)
{
    const float* x = (const float*)d_in[0];
    const float* c0w = (const float*)d_in[1];  const float* c0b = (const float*)d_in[2];
    const float* c1w = (const float*)d_in[3];  const float* g1 = (const float*)d_in[4];  const float* b1 = (const float*)d_in[5];
    const float* c2w = (const float*)d_in[6];  const float* g2 = (const float*)d_in[7];  const float* b2 = (const float*)d_in[8];
    const float* c3w = (const float*)d_in[9];  const float* g3 = (const float*)d_in[10]; const float* b3 = (const float*)d_in[11];
    const float* c4w = (const float*)d_in[12]; const float* g4 = (const float*)d_in[13]; const float* b4 = (const float*)d_in[14];
    const float* c5w = (const float*)d_in[15]; const float* g5 = (const float*)d_in[16]; const float* b5 = (const float*)d_in[17];
    const float* c6w = (const float*)d_in[18]; const float* g6 = (const float*)d_in[19]; const float* b6 = (const float*)d_in[20];
    const float* wg = (const float*)d_in[21];
    const float* bw = (const float*)d_in[22]; const float* bb = (const float*)d_in[23];
    const float* ow = (const float*)d_in[24];
    const float* cw1 = (const float*)d_in[25]; const float* cb1 = (const float*)d_in[26];
    const float* cw2 = (const float*)d_in[27]; const float* cb2 = (const float*)d_in[28];
    float* out = (float*)d_out;

    float *raw, *tok;
    __half *A0, *A1, *B0, *B1, *w0, *w1;
    cudaGetSymbolAddress((void**)&raw, g_raw);
    cudaGetSymbolAddress((void**)&tok, g_tok);
    cudaGetSymbolAddress((void**)&A0, g_A0); cudaGetSymbolAddress((void**)&A1, g_A1);
    cudaGetSymbolAddress((void**)&B0, g_B0); cudaGetSymbolAddress((void**)&B1, g_B1);
    cudaGetSymbolAddress((void**)&w0, g_w0); cudaGetSymbolAddress((void**)&w1, g_w1);

    const int SM64 = 2 * (2 * 16384 + 2 * 64 * 128);   // 98304
    cudaFuncSetAttribute(conv_mma<64>, cudaFuncAttributeMaxDynamicSharedMemorySize, SM64);

    // conv0 -> raw; prep (lrelu+split) -> A planes (NHWC C=64, 256x256)
    conv0_kernel<<<33554432 / 256, 256>>>(x, c0w, c0b, raw);
    prep_kernel<<<dim3(8 * 256, 8), 256, 32 * 65 * 4>>>(raw, 0, A0, A1, 64, 6, 256, 256);

    // conv1: 64->64 4x4 s2
    wsplit_kernel<<<(64 * 1024 + 255) / 256, 256>>>(c1w, 64, 64, 4, 4, 65536);
    conv_mma<64><<<dim3(1024, 1), 256, SM64>>>(A0, A1, w0, w1, raw,
        6, 4, 2, 256, 256, 14, 7, 64, 1024, 16);
    bnstat_kernel<<<dim3(64, 8), 256>>>(raw, 64, 16384);
    bnfin_kernel<<<1, 64>>>(g1, b1, 64, 16384);
    prep_kernel<<<dim3(8 * 128, 4), 256, 32 * 65 * 4>>>(raw, 1, B0, B1, 64, 6, 128, 128);

    // conv2: 64->128 3x3 s1
    wsplit_kernel<<<(128 * 576 + 255) / 256, 256>>>(c2w, 128, 64, 3, 3, 73728);
    conv_mma<64><<<dim3(1024, 2), 256, SM64>>>(B0, B1, w0, w1, raw,
        6, 3, 1, 128, 128, 14, 7, 128, 576, 9);
    bnstat_kernel<<<dim3(128, 8), 256>>>(raw, 128, 16384);
    bnfin_kernel<<<1, 128>>>(g2, b2, 128, 16384);
    prep_kernel<<<dim3(8 * 128, 4), 256, 32 * 129 * 4>>>(raw, 1, A0, A1, 128, 7, 128, 128);

    // conv3: 128->128 4x4 s2
    wsplit_kernel<<<(128 * 2048 + 255) / 256, 256>>>(c3w, 128, 128, 4, 4, 262144);
    conv_mma<64><<<dim3(256, 2), 256, SM64>>>(A0, A1, w0, w1, raw,
        7, 4, 2, 128, 128, 12, 6, 128, 2048, 32);
    bnstat_kernel<<<dim3(128, 8), 256>>>(raw, 128, 4096);
    bnfin_kernel<<<1, 128>>>(g3, b3, 128, 4096);
    prep_kernel<<<dim3(8 * 64, 2), 256, 32 * 129 * 4>>>(raw, 1, B0, B1, 128, 7, 64, 64);

    // conv4: 128->256 3x3 s1
    wsplit_kernel<<<(256 * 1152 + 255) / 256, 256>>>(c4w, 256, 128, 3, 3, 294912);
    conv_mma<64><<<dim3(256, 4), 256, SM64>>>(B0, B1, w0, w1, raw,
        7, 3, 1, 64, 64, 12, 6, 256, 1152, 18);
    bnstat_kernel<<<dim3(256, 8), 256>>>(raw, 256, 4096);
    bnfin_kernel<<<1, 256>>>(g4, b4, 256, 4096);
    prep_kernel<<<dim3(8 * 64, 2), 256, 32 * 257 * 4>>>(raw, 1, A0, A1, 256, 8, 64, 64);

    // conv5: 256->256 3x3 s1
    wsplit_kernel<<<(256 * 2304 + 255) / 256, 256>>>(c5w, 256, 256, 3, 3, 589824);
    conv_mma<64><<<dim3(256, 4), 256, SM64>>>(A0, A1, w0, w1, raw,
        8, 3, 1, 64, 64, 12, 6, 256, 2304, 36);
    bnstat_kernel<<<dim3(256, 8), 256>>>(raw, 256, 4096);
    bnfin_kernel<<<1, 256>>>(g5, b5, 256, 4096);
    prep_kernel<<<dim3(8 * 64, 2), 256, 32 * 257 * 4>>>(raw, 1, B0, B1, 256, 8, 64, 64);

    // conv6: 256->256 3x3 s1
    wsplit_kernel<<<(256 * 2304 + 255) / 256, 256>>>(c6w, 256, 256, 3, 3, 589824);
    conv_mma<64><<<dim3(256, 4), 256, SM64>>>(B0, B1, w0, w1, raw,
        8, 3, 1, 64, 64, 12, 6, 256, 2304, 36);
    bnstat_kernel<<<dim3(256, 8), 256>>>(raw, 256, 4096);
    bnfin_kernel<<<1, 256>>>(g6, b6, 256, 4096);
    prep_tok_kernel<<<dim3(8 * 64, 2), 256, 32 * 257 * 4>>>(raw, tok, 256, 8, 64, 64);

    // head: router -> group -> expert GEMM -> classifier
    zero_cnt_kernel<<<1, 32>>>();
    router_kernel<<<4096, 256>>>(tok, wg);
    offsets_kernel<<<1, 32>>>();
    scatter_kernel<<<128, 256>>>();
    body_kernel<<<dim3(256, 12), 512>>>(tok, bw, bb, ow, raw);  // feat -> g_raw
    cls_kernel<<<4096, 256>>>(raw, cw1, cb1, cw2, cb2, out);
}